// round 1
// baseline (speedup 1.0000x reference)
#include <cuda_runtime.h>
#include <cstdint>

#define DIM 4096
#define MTOT 16384

// Scratch (device globals — no allocation allowed)
static __device__ float g_h[(size_t)MTOT * DIM];   // LayerNorm output, tf32-rounded
static __device__ float g_wt[(size_t)DIM * DIM];   // W, tf32-rounded

__device__ __forceinline__ float f2tf32(float f) {
    uint32_t r;
    asm("cvt.rna.tf32.f32 %0, %1;" : "=r"(r) : "f"(f));
    return __uint_as_float(r);
}

// ---------------------------------------------------------------------------
// Kernel 1: pre-round W to TF32
// ---------------------------------------------------------------------------
__global__ void round_w_kernel(const float4* __restrict__ W) {
    size_t i = (size_t)blockIdx.x * blockDim.x + threadIdx.x;
    float4 v = W[i];
    float4 o;
    o.x = f2tf32(v.x); o.y = f2tf32(v.y); o.z = f2tf32(v.z); o.w = f2tf32(v.w);
    reinterpret_cast<float4*>(g_wt)[i] = o;
}

// ---------------------------------------------------------------------------
// Kernel 2: LayerNorm, one row per block (256 threads, 16 elems/thread),
// output tf32-rounded into g_h
// ---------------------------------------------------------------------------
__global__ void ln_kernel(const float* __restrict__ x,
                          const float* __restrict__ gamma,
                          const float* __restrict__ beta) {
    __shared__ float rs[8], rq[8];
    const int row = blockIdx.x;
    const int tid = threadIdx.x;
    const float4* xr = reinterpret_cast<const float4*>(x + (size_t)row * DIM);

    float4 v[4];
    float s = 0.f, sq = 0.f;
#pragma unroll
    for (int i = 0; i < 4; i++) {
        v[i] = xr[tid + i * 256];
        s  += v[i].x + v[i].y + v[i].z + v[i].w;
        sq += v[i].x * v[i].x + v[i].y * v[i].y + v[i].z * v[i].z + v[i].w * v[i].w;
    }
#pragma unroll
    for (int off = 16; off > 0; off >>= 1) {
        s  += __shfl_xor_sync(0xffffffffu, s, off);
        sq += __shfl_xor_sync(0xffffffffu, sq, off);
    }
    if ((tid & 31) == 0) { rs[tid >> 5] = s; rq[tid >> 5] = sq; }
    __syncthreads();
    float ts = 0.f, tq = 0.f;
#pragma unroll
    for (int i = 0; i < 8; i++) { ts += rs[i]; tq += rq[i]; }

    const float mean = ts * (1.0f / DIM);
    const float var  = tq * (1.0f / DIM) - mean * mean;
    const float inv  = rsqrtf(var + 1e-5f);

    const float4* gp = reinterpret_cast<const float4*>(gamma);
    const float4* bp = reinterpret_cast<const float4*>(beta);
    float4* hr = reinterpret_cast<float4*>(g_h + (size_t)row * DIM);
#pragma unroll
    for (int i = 0; i < 4; i++) {
        const int c = tid + i * 256;
        float4 g = gp[c], be = bp[c];
        float4 o;
        o.x = f2tf32((v[i].x - mean) * inv * g.x + be.x);
        o.y = f2tf32((v[i].y - mean) * inv * g.y + be.y);
        o.z = f2tf32((v[i].z - mean) * inv * g.z + be.z);
        o.w = f2tf32((v[i].w - mean) * inv * g.w + be.w);
        hr[c] = o;
    }
}

// ---------------------------------------------------------------------------
// Kernel 3: GEMM  out[m,n] = relu( sum_k h[m,k] * W[n,k] + bias[n] )
// 128x128x32 tile, 256 threads, 8 warps (4x2), mma.m16n8k8 tf32,
// cp.async double-buffered
// ---------------------------------------------------------------------------
#define BM 128
#define BN 128
#define BK 32
#define SPAD 36                       // 32 + 4 pad: conflict-free frag loads
#define STAGE ((BM + BN) * SPAD)      // floats per stage = 9216
#define SMEM_BYTES (2 * STAGE * 4)    // 73728 B

__device__ __forceinline__ void cp_async16(uint32_t smem_dst, const void* gptr) {
    asm volatile("cp.async.cg.shared.global [%0], [%1], 16;\n"
                 :: "r"(smem_dst), "l"(gptr));
}

__device__ __forceinline__ void mma_tf32(float* c, const uint32_t* a,
                                         uint32_t b0, uint32_t b1) {
    asm volatile(
        "mma.sync.aligned.m16n8k8.row.col.f32.tf32.tf32.f32 "
        "{%0,%1,%2,%3}, {%4,%5,%6,%7}, {%8,%9}, {%0,%1,%2,%3};\n"
        : "+f"(c[0]), "+f"(c[1]), "+f"(c[2]), "+f"(c[3])
        : "r"(a[0]), "r"(a[1]), "r"(a[2]), "r"(a[3]), "r"(b0), "r"(b1));
}

__global__ void __launch_bounds__(256, 1)
gemm_kernel(const float* __restrict__ bias, float* __restrict__ out) {
    extern __shared__ float smem[];
    const int tid  = threadIdx.x;
    const int lane = tid & 31;
    const int wid  = tid >> 5;
    const int warp_m = wid >> 1;   // 0..3  -> 32 rows each
    const int warp_n = wid & 1;    // 0..1  -> 64 cols each
    const int bn = blockIdx.x;     // N tiles fastest: same A tile per wave
    const int bm = blockIdx.y;

    const float* Abase = g_h  + (size_t)(bm * BM) * DIM;
    const float* Bbase = g_wt + (size_t)(bn * BN) * DIM;
    const uint32_t smem_u = (uint32_t)__cvta_generic_to_shared(smem);

    float acc[2][8][4];
#pragma unroll
    for (int i = 0; i < 2; i++)
#pragma unroll
        for (int j = 0; j < 8; j++)
#pragma unroll
            for (int r = 0; r < 4; r++) acc[i][j][r] = 0.f;

    // per-thread staging: 4 chunks of A + 4 chunks of B (16B each)
    auto issue = [&](int kt, int s) {
        const int k0 = kt * BK;
        const uint32_t sa = smem_u + (uint32_t)(s * STAGE) * 4u;
        const uint32_t sb = sa + (uint32_t)(BM * SPAD) * 4u;
#pragma unroll
        for (int i = 0; i < 4; i++) {
            const int q  = tid + i * 256;
            const int r  = q >> 3;         // row 0..127
            const int kc = (q & 7) * 4;    // k offset (floats)
            cp_async16(sa + (uint32_t)(r * SPAD + kc) * 4u,
                       Abase + (size_t)r * DIM + k0 + kc);
            cp_async16(sb + (uint32_t)(r * SPAD + kc) * 4u,
                       Bbase + (size_t)r * DIM + k0 + kc);
        }
        asm volatile("cp.async.commit_group;\n" ::);
    };

    const int NK = DIM / BK;  // 128
    issue(0, 0);

    for (int kt = 0; kt < NK; kt++) {
        const int s = kt & 1;
        if (kt + 1 < NK) {
            issue(kt + 1, (kt + 1) & 1);
            asm volatile("cp.async.wait_group 1;\n" ::);
        } else {
            asm volatile("cp.async.wait_group 0;\n" ::);
        }
        __syncthreads();

        const float* As = smem + s * STAGE;
        const float* Bs = As + BM * SPAD;
#pragma unroll
        for (int ks = 0; ks < 4; ks++) {
            const int k = ks * 8 + (lane & 3);
            uint32_t a[2][4];
#pragma unroll
            for (int mi = 0; mi < 2; mi++) {
                const float* p = As + (warp_m * 32 + mi * 16 + (lane >> 2)) * SPAD + k;
                a[mi][0] = __float_as_uint(p[0]);
                a[mi][1] = __float_as_uint(p[8 * SPAD]);
                a[mi][2] = __float_as_uint(p[4]);
                a[mi][3] = __float_as_uint(p[8 * SPAD + 4]);
            }
#pragma unroll
            for (int nj = 0; nj < 8; nj++) {
                const float* p = Bs + (warp_n * 64 + nj * 8 + (lane >> 2)) * SPAD + k;
                const uint32_t b0 = __float_as_uint(p[0]);
                const uint32_t b1 = __float_as_uint(p[4]);
#pragma unroll
                for (int mi = 0; mi < 2; mi++)
                    mma_tf32(acc[mi][nj], a[mi], b0, b1);
            }
        }
        __syncthreads();
    }

    // epilogue: bias + ReLU, float2 stores
    const int m0 = bm * BM + warp_m * 32;
    const int n0 = bn * BN + warp_n * 64;
#pragma unroll
    for (int nj = 0; nj < 8; nj++) {
        const int n = n0 + nj * 8 + (lane & 3) * 2;
        const float b0 = bias[n];
        const float b1 = bias[n + 1];
#pragma unroll
        for (int mi = 0; mi < 2; mi++) {
            const int m = m0 + mi * 16 + (lane >> 2);
            float2 r0, r1;
            r0.x = fmaxf(acc[mi][nj][0] + b0, 0.f);
            r0.y = fmaxf(acc[mi][nj][1] + b1, 0.f);
            r1.x = fmaxf(acc[mi][nj][2] + b0, 0.f);
            r1.y = fmaxf(acc[mi][nj][3] + b1, 0.f);
            *reinterpret_cast<float2*>(out + (size_t)m * DIM + n) = r0;
            *reinterpret_cast<float2*>(out + (size_t)(m + 8) * DIM + n) = r1;
        }
    }
}

// ---------------------------------------------------------------------------
extern "C" void kernel_launch(void* const* d_in, const int* in_sizes, int n_in,
                              void* d_out, int out_size) {
    const float* x     = (const float*)d_in[0];
    const float* W     = (const float*)d_in[1];
    const float* bias  = (const float*)d_in[2];
    const float* gamma = (const float*)d_in[3];
    const float* beta  = (const float*)d_in[4];
    float* out = (float*)d_out;

    round_w_kernel<<<(DIM * (size_t)DIM) / (256 * 4), 256>>>(
        reinterpret_cast<const float4*>(W));
    ln_kernel<<<MTOT, 256>>>(x, gamma, beta);

    cudaFuncSetAttribute(gemm_kernel,
                         cudaFuncAttributeMaxDynamicSharedMemorySize, SMEM_BYTES);
    dim3 grid(DIM / BN, MTOT / BM);  // (32, 128): N fastest for L2 reuse of A
    gemm_kernel<<<grid, 256, SMEM_BYTES>>>(bias, out);
}

// round 9
// speedup vs baseline: 1.0258x; 1.0258x over previous
#include <cuda_runtime.h>
#include <cstdint>

#define DIM  4096
#define MTOT 16384

// Scratch (device globals — no allocation allowed)
static __device__ float g_h[(size_t)MTOT * DIM];   // LayerNorm output, tf32-rounded
static __device__ float g_wt[(size_t)DIM * DIM];   // W, tf32-rounded

__device__ __forceinline__ float f2tf32(float f) {
    uint32_t r;
    asm("cvt.rna.tf32.f32 %0, %1;" : "=r"(r) : "f"(f));
    return __uint_as_float(r);
}

// ---------------------------------------------------------------------------
// Kernel 1: pre-round W to TF32
// ---------------------------------------------------------------------------
__global__ void round_w_kernel(const float4* __restrict__ W) {
    size_t i = (size_t)blockIdx.x * blockDim.x + threadIdx.x;
    float4 v = W[i];
    float4 o;
    o.x = f2tf32(v.x); o.y = f2tf32(v.y); o.z = f2tf32(v.z); o.w = f2tf32(v.w);
    reinterpret_cast<float4*>(g_wt)[i] = o;
}

// ---------------------------------------------------------------------------
// Kernel 2: LayerNorm, one row per block (256 threads, 16 elems/thread),
// output tf32-rounded into g_h
// ---------------------------------------------------------------------------
__global__ void ln_kernel(const float* __restrict__ x,
                          const float* __restrict__ gamma,
                          const float* __restrict__ beta) {
    __shared__ float rs[8], rq[8];
    const int row = blockIdx.x;
    const int tid = threadIdx.x;
    const float4* xr = reinterpret_cast<const float4*>(x + (size_t)row * DIM);

    float4 v[4];
    float s = 0.f, sq = 0.f;
#pragma unroll
    for (int i = 0; i < 4; i++) {
        v[i] = xr[tid + i * 256];
        s  += v[i].x + v[i].y + v[i].z + v[i].w;
        sq += v[i].x * v[i].x + v[i].y * v[i].y + v[i].z * v[i].z + v[i].w * v[i].w;
    }
#pragma unroll
    for (int off = 16; off > 0; off >>= 1) {
        s  += __shfl_xor_sync(0xffffffffu, s, off);
        sq += __shfl_xor_sync(0xffffffffu, sq, off);
    }
    if ((tid & 31) == 0) { rs[tid >> 5] = s; rq[tid >> 5] = sq; }
    __syncthreads();
    float ts = 0.f, tq = 0.f;
#pragma unroll
    for (int i = 0; i < 8; i++) { ts += rs[i]; tq += rq[i]; }

    const float mean = ts * (1.0f / DIM);
    const float var  = tq * (1.0f / DIM) - mean * mean;
    const float inv  = rsqrtf(var + 1e-5f);

    const float4* gp = reinterpret_cast<const float4*>(gamma);
    const float4* bp = reinterpret_cast<const float4*>(beta);
    float4* hr = reinterpret_cast<float4*>(g_h + (size_t)row * DIM);
#pragma unroll
    for (int i = 0; i < 4; i++) {
        const int c = tid + i * 256;
        float4 g = gp[c], be = bp[c];
        float4 o;
        o.x = f2tf32((v[i].x - mean) * inv * g.x + be.x);
        o.y = f2tf32((v[i].y - mean) * inv * g.y + be.y);
        o.z = f2tf32((v[i].z - mean) * inv * g.z + be.z);
        o.w = f2tf32((v[i].w - mean) * inv * g.w + be.w);
        hr[c] = o;
    }
}

// ---------------------------------------------------------------------------
// Kernel 3: GEMM  out[m,n] = relu( sum_k h[m,k] * W[n,k] + bias[n] )
// 256x128x32 tile, 512 threads, 16 warps (8x2), mma.m16n8k8 tf32,
// 3-stage cp.async pipeline
// ---------------------------------------------------------------------------
#define BM 256
#define BN 128
#define BK 32
#define NSTG 3
#define SPAD 36                        // 32 + 4 pad: conflict-free frag loads
#define STAGE ((BM + BN) * SPAD)       // floats per stage = 13824
#define SMEM_BYTES (NSTG * STAGE * 4)  // 165888 B

__device__ __forceinline__ void cp_async16(uint32_t smem_dst, const void* gptr) {
    asm volatile("cp.async.cg.shared.global [%0], [%1], 16;\n"
                 :: "r"(smem_dst), "l"(gptr));
}

__device__ __forceinline__ void mma_tf32(float* c, const uint32_t* a,
                                         uint32_t b0, uint32_t b1) {
    asm volatile(
        "mma.sync.aligned.m16n8k8.row.col.f32.tf32.tf32.f32 "
        "{%0,%1,%2,%3}, {%4,%5,%6,%7}, {%8,%9}, {%0,%1,%2,%3};\n"
        : "+f"(c[0]), "+f"(c[1]), "+f"(c[2]), "+f"(c[3])
        : "r"(a[0]), "r"(a[1]), "r"(a[2]), "r"(a[3]), "r"(b0), "r"(b1));
}

// streaming store (evict-first): keep the 256MB output out of L2
__device__ __forceinline__ void st_cs_f2(float* p, float2 v) {
    asm volatile("st.global.cs.v2.f32 [%0], {%1, %2};" :: "l"(p), "f"(v.x), "f"(v.y)
                 : "memory");
}

__global__ void __launch_bounds__(512, 1)
gemm_kernel(const float* __restrict__ bias, float* __restrict__ out) {
    extern __shared__ float smem[];
    const int tid  = threadIdx.x;
    const int lane = tid & 31;
    const int wid  = tid >> 5;
    const int warp_m = wid >> 1;   // 0..7  -> 32 rows each
    const int warp_n = wid & 1;    // 0..1  -> 64 cols each
    const int bn = blockIdx.x;     // N tiles fastest: A-tile L2 reuse per wave
    const int bm = blockIdx.y;

    const float* Abase = g_h  + (size_t)(bm * BM) * DIM;
    const float* Bbase = g_wt + (size_t)(bn * BN) * DIM;
    const uint32_t smem_u = (uint32_t)__cvta_generic_to_shared(smem);

    float acc[2][8][4];
#pragma unroll
    for (int i = 0; i < 2; i++)
#pragma unroll
        for (int j = 0; j < 8; j++)
#pragma unroll
            for (int r = 0; r < 4; r++) acc[i][j][r] = 0.f;

    // staging: (256+128) rows x 8 chunks of 16B = 3072 chunks; 6 per thread
    auto issue = [&](int kt) {
        const int s  = kt % NSTG;
        const int k0 = kt * BK;
        const uint32_t sa  = smem_u + (uint32_t)(s * STAGE) * 4u;
        const uint32_t sb2 = sa + (uint32_t)(BM * SPAD) * 4u;
#pragma unroll
        for (int i = 0; i < 6; i++) {
            const int c = tid + i * 512;
            if (c < BM * 8) {
                const int r  = c >> 3;
                const int kc = (c & 7) * 4;
                cp_async16(sa + (uint32_t)(r * SPAD + kc) * 4u,
                           Abase + (size_t)r * DIM + k0 + kc);
            } else {
                const int c2 = c - BM * 8;
                const int r  = c2 >> 3;
                const int kc = (c2 & 7) * 4;
                cp_async16(sb2 + (uint32_t)(r * SPAD + kc) * 4u,
                           Bbase + (size_t)r * DIM + k0 + kc);
            }
        }
        asm volatile("cp.async.commit_group;\n" ::);
    };

    const int NK = DIM / BK;  // 128
    issue(0);
    issue(1);

    for (int kt = 0; kt < NK; kt++) {
        if (kt + 2 < NK) {
            issue(kt + 2);
            asm volatile("cp.async.wait_group 2;\n" ::);
        } else {
            asm volatile("cp.async.wait_group 0;\n" ::);
        }
        __syncthreads();

        const float* As = smem + (kt % NSTG) * STAGE;
        const float* Bs = As + BM * SPAD;
#pragma unroll
        for (int ks = 0; ks < 4; ks++) {
            const int k = ks * 8 + (lane & 3);
            uint32_t a[2][4];
#pragma unroll
            for (int mi = 0; mi < 2; mi++) {
                const float* p = As + (warp_m * 32 + mi * 16 + (lane >> 2)) * SPAD + k;
                a[mi][0] = __float_as_uint(p[0]);
                a[mi][1] = __float_as_uint(p[8 * SPAD]);
                a[mi][2] = __float_as_uint(p[4]);
                a[mi][3] = __float_as_uint(p[8 * SPAD + 4]);
            }
#pragma unroll
            for (int nj = 0; nj < 8; nj++) {
                const float* p = Bs + (warp_n * 64 + nj * 8 + (lane >> 2)) * SPAD + k;
                const uint32_t b0 = __float_as_uint(p[0]);
                const uint32_t b1 = __float_as_uint(p[4]);
#pragma unroll
                for (int mi = 0; mi < 2; mi++)
                    mma_tf32(acc[mi][nj], a[mi], b0, b1);
            }
        }
        __syncthreads();
    }

    // epilogue: bias + ReLU, streaming float2 stores
    const int m0 = bm * BM + warp_m * 32;
    const int n0 = bn * BN + warp_n * 64;
#pragma unroll
    for (int nj = 0; nj < 8; nj++) {
        const int n = n0 + nj * 8 + (lane & 3) * 2;
        const float b0 = bias[n];
        const float b1 = bias[n + 1];
#pragma unroll
        for (int mi = 0; mi < 2; mi++) {
            const int m = m0 + mi * 16 + (lane >> 2);
            float2 r0, r1;
            r0.x = fmaxf(acc[mi][nj][0] + b0, 0.f);
            r0.y = fmaxf(acc[mi][nj][1] + b1, 0.f);
            r1.x = fmaxf(acc[mi][nj][2] + b0, 0.f);
            r1.y = fmaxf(acc[mi][nj][3] + b1, 0.f);
            st_cs_f2(out + (size_t)m * DIM + n, r0);
            st_cs_f2(out + (size_t)(m + 8) * DIM + n, r1);
        }
    }
}

// ---------------------------------------------------------------------------
extern "C" void kernel_launch(void* const* d_in, const int* in_sizes, int n_in,
                              void* d_out, int out_size) {
    const float* x     = (const float*)d_in[0];
    const float* W     = (const float*)d_in[1];
    const float* bias  = (const float*)d_in[2];
    const float* gamma = (const float*)d_in[3];
    const float* beta  = (const float*)d_in[4];
    float* out = (float*)d_out;

    round_w_kernel<<<(DIM * (size_t)DIM) / (256 * 4), 256>>>(
        reinterpret_cast<const float4*>(W));
    ln_kernel<<<MTOT, 256>>>(x, gamma, beta);

    cudaFuncSetAttribute(gemm_kernel,
                         cudaFuncAttributeMaxDynamicSharedMemorySize, SMEM_BYTES);
    dim3 grid(DIM / BN, MTOT / BM);  // (32, 64)
    gemm_kernel<<<grid, 512, SMEM_BYTES>>>(bias, out);
}

// round 10
// speedup vs baseline: 1.1102x; 1.0823x over previous
#include <cuda_runtime.h>
#include <cstdint>

#define DIM  4096
#define MTOT 16384

// Scratch (device globals — no allocation allowed)
static __device__ float g_h[(size_t)MTOT * DIM];   // LayerNorm output, tf32-rounded
static __device__ float g_wt[(size_t)DIM * DIM];   // W, tf32-rounded

__device__ __forceinline__ float f2tf32(float f) {
    uint32_t r;
    asm("cvt.rna.tf32.f32 %0, %1;" : "=r"(r) : "f"(f));
    return __uint_as_float(r);
}

// ---------------------------------------------------------------------------
// Kernel 1: pre-round W to TF32
// ---------------------------------------------------------------------------
__global__ void round_w_kernel(const float4* __restrict__ W) {
    size_t i = (size_t)blockIdx.x * blockDim.x + threadIdx.x;
    float4 v = W[i];
    float4 o;
    o.x = f2tf32(v.x); o.y = f2tf32(v.y); o.z = f2tf32(v.z); o.w = f2tf32(v.w);
    reinterpret_cast<float4*>(g_wt)[i] = o;
}

// ---------------------------------------------------------------------------
// Kernel 2: LayerNorm, one row per block (256 threads, 16 elems/thread),
// output tf32-rounded into g_h
// ---------------------------------------------------------------------------
__global__ void ln_kernel(const float* __restrict__ x,
                          const float* __restrict__ gamma,
                          const float* __restrict__ beta) {
    __shared__ float rs[8], rq[8];
    const int row = blockIdx.x;
    const int tid = threadIdx.x;
    const float4* xr = reinterpret_cast<const float4*>(x + (size_t)row * DIM);

    float4 v[4];
    float s = 0.f, sq = 0.f;
#pragma unroll
    for (int i = 0; i < 4; i++) {
        v[i] = xr[tid + i * 256];
        s  += v[i].x + v[i].y + v[i].z + v[i].w;
        sq += v[i].x * v[i].x + v[i].y * v[i].y + v[i].z * v[i].z + v[i].w * v[i].w;
    }
#pragma unroll
    for (int off = 16; off > 0; off >>= 1) {
        s  += __shfl_xor_sync(0xffffffffu, s, off);
        sq += __shfl_xor_sync(0xffffffffu, sq, off);
    }
    if ((tid & 31) == 0) { rs[tid >> 5] = s; rq[tid >> 5] = sq; }
    __syncthreads();
    float ts = 0.f, tq = 0.f;
#pragma unroll
    for (int i = 0; i < 8; i++) { ts += rs[i]; tq += rq[i]; }

    const float mean = ts * (1.0f / DIM);
    const float var  = tq * (1.0f / DIM) - mean * mean;
    const float inv  = rsqrtf(var + 1e-5f);

    const float4* gp = reinterpret_cast<const float4*>(gamma);
    const float4* bp = reinterpret_cast<const float4*>(beta);
    float4* hr = reinterpret_cast<float4*>(g_h + (size_t)row * DIM);
#pragma unroll
    for (int i = 0; i < 4; i++) {
        const int c = tid + i * 256;
        float4 g = gp[c], be = bp[c];
        float4 o;
        o.x = f2tf32((v[i].x - mean) * inv * g.x + be.x);
        o.y = f2tf32((v[i].y - mean) * inv * g.y + be.y);
        o.z = f2tf32((v[i].z - mean) * inv * g.z + be.z);
        o.w = f2tf32((v[i].w - mean) * inv * g.w + be.w);
        hr[c] = o;
    }
}

// ---------------------------------------------------------------------------
// Kernel 3: GEMM  out[m,n] = relu( sum_k h[m,k] * W[n,k] + bias[n] )
// 256x128x32 CTA tile, 256 threads, 8 warps (4x2), warp tile 64x64,
// mma.m16n8k8 tf32, 3-stage cp.async pipeline.
// ---------------------------------------------------------------------------
#define BM 256
#define BN 128
#define BK 32
#define NSTG 3
#define SPAD 36                        // 32 + 4 pad: conflict-free frag loads
#define STAGE ((BM + BN) * SPAD)       // floats per stage = 13824
#define SMEM_BYTES (NSTG * STAGE * 4)  // 165888 B

__device__ __forceinline__ void cp_async16(uint32_t smem_dst, const void* gptr) {
    asm volatile("cp.async.cg.shared.global [%0], [%1], 16;\n"
                 :: "r"(smem_dst), "l"(gptr));
}

__device__ __forceinline__ void mma_tf32(float* c, const uint32_t* a,
                                         uint32_t b0, uint32_t b1) {
    asm volatile(
        "mma.sync.aligned.m16n8k8.row.col.f32.tf32.tf32.f32 "
        "{%0,%1,%2,%3}, {%4,%5,%6,%7}, {%8,%9}, {%0,%1,%2,%3};\n"
        : "+f"(c[0]), "+f"(c[1]), "+f"(c[2]), "+f"(c[3])
        : "r"(a[0]), "r"(a[1]), "r"(a[2]), "r"(a[3]), "r"(b0), "r"(b1));
}

// streaming store (evict-first): keep the 256MB output out of L2
__device__ __forceinline__ void st_cs_f2(float* p, float2 v) {
    asm volatile("st.global.cs.v2.f32 [%0], {%1, %2};" :: "l"(p), "f"(v.x), "f"(v.y)
                 : "memory");
}

__global__ void __launch_bounds__(256, 1)
gemm_kernel(const float* __restrict__ bias, float* __restrict__ out) {
    extern __shared__ float smem[];
    const int tid  = threadIdx.x;
    const int lane = tid & 31;
    const int wid  = tid >> 5;
    const int warp_m = wid >> 1;   // 0..3 -> 64 rows each
    const int warp_n = wid & 1;    // 0..1 -> 64 cols each
    const int bn = blockIdx.x;     // N tiles fastest: A-tile L2 reuse per wave
    const int bm = blockIdx.y;

    const float* Abase = g_h  + (size_t)(bm * BM) * DIM;
    const float* Bbase = g_wt + (size_t)(bn * BN) * DIM;
    const uint32_t smem_u = (uint32_t)__cvta_generic_to_shared(smem);

    float acc[4][8][4];
#pragma unroll
    for (int i = 0; i < 4; i++)
#pragma unroll
        for (int j = 0; j < 8; j++)
#pragma unroll
            for (int r = 0; r < 4; r++) acc[i][j][r] = 0.f;

    // staging: (256+128) rows x 8 chunks of 16B = 3072 chunks; 12 per thread
    auto issue = [&](int kt) {
        const int s  = kt % NSTG;
        const int k0 = kt * BK;
        const uint32_t sa  = smem_u + (uint32_t)(s * STAGE) * 4u;
        const uint32_t sb2 = sa + (uint32_t)(BM * SPAD) * 4u;
#pragma unroll
        for (int i = 0; i < 12; i++) {
            const int c = tid + i * 256;
            if (c < BM * 8) {
                const int r  = c >> 3;
                const int kc = (c & 7) * 4;
                cp_async16(sa + (uint32_t)(r * SPAD + kc) * 4u,
                           Abase + (size_t)r * DIM + k0 + kc);
            } else {
                const int c2 = c - BM * 8;
                const int r  = c2 >> 3;
                const int kc = (c2 & 7) * 4;
                cp_async16(sb2 + (uint32_t)(r * SPAD + kc) * 4u,
                           Bbase + (size_t)r * DIM + k0 + kc);
            }
        }
        asm volatile("cp.async.commit_group;\n" ::);
    };

    const int NK = DIM / BK;  // 128
    issue(0);
    issue(1);

    for (int kt = 0; kt < NK; kt++) {
        if (kt + 2 < NK) {
            issue(kt + 2);
            asm volatile("cp.async.wait_group 2;\n" ::);
        } else {
            asm volatile("cp.async.wait_group 0;\n" ::);
        }
        __syncthreads();

        const float* As = smem + (kt % NSTG) * STAGE;
        const float* Bs = As + BM * SPAD;
#pragma unroll
        for (int ks = 0; ks < 4; ks++) {
            const int k = ks * 8 + (lane & 3);
            // A fragments: 4 m16 tiles (64 rows)
            uint32_t a[4][4];
#pragma unroll
            for (int mi = 0; mi < 4; mi++) {
                const float* p = As + (warp_m * 64 + mi * 16 + (lane >> 2)) * SPAD + k;
                a[mi][0] = __float_as_uint(p[0]);
                a[mi][1] = __float_as_uint(p[8 * SPAD]);
                a[mi][2] = __float_as_uint(p[4]);
                a[mi][3] = __float_as_uint(p[8 * SPAD + 4]);
            }
            // B fragments: 8 n8 tiles (64 cols)
            uint32_t b[8][2];
#pragma unroll
            for (int nj = 0; nj < 8; nj++) {
                const float* p = Bs + (warp_n * 64 + nj * 8 + (lane >> 2)) * SPAD + k;
                b[nj][0] = __float_as_uint(p[0]);
                b[nj][1] = __float_as_uint(p[4]);
            }
#pragma unroll
            for (int nj = 0; nj < 8; nj++)
#pragma unroll
                for (int mi = 0; mi < 4; mi++)
                    mma_tf32(acc[mi][nj], a[mi], b[nj][0], b[nj][1]);
        }
        __syncthreads();
    }

    // epilogue: bias + ReLU, streaming float2 stores
    const int m0 = bm * BM + warp_m * 64;
    const int n0 = bn * BN + warp_n * 64;
#pragma unroll
    for (int nj = 0; nj < 8; nj++) {
        const int n = n0 + nj * 8 + (lane & 3) * 2;
        const float b0 = bias[n];
        const float b1 = bias[n + 1];
#pragma unroll
        for (int mi = 0; mi < 4; mi++) {
            const int m = m0 + mi * 16 + (lane >> 2);
            float2 r0, r1;
            r0.x = fmaxf(acc[mi][nj][0] + b0, 0.f);
            r0.y = fmaxf(acc[mi][nj][1] + b1, 0.f);
            r1.x = fmaxf(acc[mi][nj][2] + b0, 0.f);
            r1.y = fmaxf(acc[mi][nj][3] + b1, 0.f);
            st_cs_f2(out + (size_t)m * DIM + n, r0);
            st_cs_f2(out + (size_t)(m + 8) * DIM + n, r1);
        }
    }
}

// ---------------------------------------------------------------------------
extern "C" void kernel_launch(void* const* d_in, const int* in_sizes, int n_in,
                              void* d_out, int out_size) {
    const float* x     = (const float*)d_in[0];
    const float* W     = (const float*)d_in[1];
    const float* bias  = (const float*)d_in[2];
    const float* gamma = (const float*)d_in[3];
    const float* beta  = (const float*)d_in[4];
    float* out = (float*)d_out;

    round_w_kernel<<<(DIM * (size_t)DIM) / (256 * 4), 256>>>(
        reinterpret_cast<const float4*>(W));
    ln_kernel<<<MTOT, 256>>>(x, gamma, beta);

    cudaFuncSetAttribute(gemm_kernel,
                         cudaFuncAttributeMaxDynamicSharedMemorySize, SMEM_BYTES);
    dim3 grid(DIM / BN, MTOT / BM);  // (32, 64)
    gemm_kernel<<<grid, 256, SMEM_BYTES>>>(bias, out);
}

// round 13
// speedup vs baseline: 2.1860x; 1.9690x over previous
#include <cuda_runtime.h>
#include <cuda_fp16.h>
#include <cstdint>

#define DIM  4096
#define MTOT 16384

// Scratch (device globals — no allocation allowed)
static __device__ __half g_h[(size_t)MTOT * DIM];   // LN output, fp16
static __device__ __half g_wt[(size_t)DIM * DIM];   // W, fp16

// ---------------------------------------------------------------------------
// Kernel 1: W -> fp16
// ---------------------------------------------------------------------------
__global__ void round_w_kernel(const float4* __restrict__ W) {
    size_t i = (size_t)blockIdx.x * blockDim.x + threadIdx.x;
    float4 v = W[i];
    __half2 h0 = __floats2half2_rn(v.x, v.y);
    __half2 h1 = __floats2half2_rn(v.z, v.w);
    uint2 o;
    o.x = *reinterpret_cast<uint32_t*>(&h0);
    o.y = *reinterpret_cast<uint32_t*>(&h1);
    reinterpret_cast<uint2*>(g_wt)[i] = o;
}

// ---------------------------------------------------------------------------
// Kernel 2: LayerNorm -> fp16 into g_h
// ---------------------------------------------------------------------------
__global__ void ln_kernel(const float* __restrict__ x,
                          const float* __restrict__ gamma,
                          const float* __restrict__ beta) {
    __shared__ float rs[8], rq[8];
    const int row = blockIdx.x;
    const int tid = threadIdx.x;
    const float4* xr = reinterpret_cast<const float4*>(x + (size_t)row * DIM);

    float4 v[4];
    float s = 0.f, sq = 0.f;
#pragma unroll
    for (int i = 0; i < 4; i++) {
        v[i] = xr[tid + i * 256];
        s  += v[i].x + v[i].y + v[i].z + v[i].w;
        sq += v[i].x * v[i].x + v[i].y * v[i].y + v[i].z * v[i].z + v[i].w * v[i].w;
    }
#pragma unroll
    for (int off = 16; off > 0; off >>= 1) {
        s  += __shfl_xor_sync(0xffffffffu, s, off);
        sq += __shfl_xor_sync(0xffffffffu, sq, off);
    }
    if ((tid & 31) == 0) { rs[tid >> 5] = s; rq[tid >> 5] = sq; }
    __syncthreads();
    float ts = 0.f, tq = 0.f;
#pragma unroll
    for (int i = 0; i < 8; i++) { ts += rs[i]; tq += rq[i]; }

    const float mean = ts * (1.0f / DIM);
    const float var  = tq * (1.0f / DIM) - mean * mean;
    const float inv  = rsqrtf(var + 1e-5f);

    const float4* gp = reinterpret_cast<const float4*>(gamma);
    const float4* bp = reinterpret_cast<const float4*>(beta);
    uint2* hr = reinterpret_cast<uint2*>(g_h + (size_t)row * DIM);
#pragma unroll
    for (int i = 0; i < 4; i++) {
        const int c = tid + i * 256;
        float4 g = gp[c], be = bp[c];
        __half2 h0 = __floats2half2_rn((v[i].x - mean) * inv * g.x + be.x,
                                       (v[i].y - mean) * inv * g.y + be.y);
        __half2 h1 = __floats2half2_rn((v[i].z - mean) * inv * g.z + be.z,
                                       (v[i].w - mean) * inv * g.w + be.w);
        uint2 o;
        o.x = *reinterpret_cast<uint32_t*>(&h0);
        o.y = *reinterpret_cast<uint32_t*>(&h1);
        hr[c] = o;
    }
}

// ---------------------------------------------------------------------------
// Kernel 3: GEMM  out[m,n] = relu( sum_k h[m,k] * W[n,k] + bias[n] )
// fp16 inputs, fp32 accum. 128x128x64 CTA tile, 256 threads, 8 warps (4x2),
// warp tile 32x64, mma.m16n8k16.f16, 3-stage cp.async, 2 CTAs/SM.
// ---------------------------------------------------------------------------
#define BM 128
#define BN 128
#define BKH 64                           // halfs per k-tile (128 B)
#define NSTG 3
#define SPADH 72                         // halfs per smem row (+8 pad)
#define STAGE_H ((BM + BN) * SPADH)      // halfs per stage = 18432
#define SMEM_BYTES (NSTG * STAGE_H * 2)  // 110592 B

__device__ __forceinline__ void cp_async16(uint32_t smem_dst, const void* gptr) {
    asm volatile("cp.async.cg.shared.global [%0], [%1], 16;\n"
                 :: "r"(smem_dst), "l"(gptr));
}

__device__ __forceinline__ void mma_f16(float* c, const uint32_t* a,
                                        uint32_t b0, uint32_t b1) {
    asm volatile(
        "mma.sync.aligned.m16n8k16.row.col.f32.f16.f16.f32 "
        "{%0,%1,%2,%3}, {%4,%5,%6,%7}, {%8,%9}, {%0,%1,%2,%3};\n"
        : "+f"(c[0]), "+f"(c[1]), "+f"(c[2]), "+f"(c[3])
        : "r"(a[0]), "r"(a[1]), "r"(a[2]), "r"(a[3]), "r"(b0), "r"(b1));
}

__device__ __forceinline__ void st_cs_f2(float* p, float2 v) {
    asm volatile("st.global.cs.v2.f32 [%0], {%1, %2};" :: "l"(p), "f"(v.x), "f"(v.y)
                 : "memory");
}

__global__ void __launch_bounds__(256, 2)
gemm_kernel(const float* __restrict__ bias, float* __restrict__ out) {
    extern __shared__ __half smem[];
    const int tid  = threadIdx.x;
    const int lane = tid & 31;
    const int wid  = tid >> 5;
    const int warp_m = wid >> 1;   // 0..3 -> 32 rows each
    const int warp_n = wid & 1;    // 0..1 -> 64 cols each
    const int bn = blockIdx.x;     // N fastest: A-tile L2 reuse per wave
    const int bm = blockIdx.y;

    const __half* Abase = g_h  + (size_t)(bm * BM) * DIM;
    const __half* Bbase = g_wt + (size_t)(bn * BN) * DIM;
    const uint32_t smem_u = (uint32_t)__cvta_generic_to_shared(smem);

    float acc[2][8][4];
#pragma unroll
    for (int i = 0; i < 2; i++)
#pragma unroll
        for (int j = 0; j < 8; j++)
#pragma unroll
            for (int r = 0; r < 4; r++) acc[i][j][r] = 0.f;

    // staging: 256 rows x 64 halfs = 2048 chunks of 16B (8 halfs); 8 per thread
    auto issue = [&](int kt) {
        const int s  = kt % NSTG;
        const int k0 = kt * BKH;
        const uint32_t sbase = smem_u + (uint32_t)(s * STAGE_H) * 2u;
#pragma unroll
        for (int i = 0; i < 8; i++) {
            const int c = tid + i * 256;
            const int r = c >> 3;          // 0..255
            const int q = (c & 7) * 8;     // half offset within row
            const uint32_t dst = sbase + (uint32_t)(r * SPADH + q) * 2u;
            const __half* src = (r < BM)
                ? Abase + (size_t)r * DIM + k0 + q
                : Bbase + (size_t)(r - BM) * DIM + k0 + q;
            cp_async16(dst, src);
        }
        asm volatile("cp.async.commit_group;\n" ::);
    };

    const int NK = DIM / BKH;  // 64
    issue(0);
    issue(1);

    for (int kt = 0; kt < NK; kt++) {
        if (kt + 2 < NK) {
            issue(kt + 2);
            asm volatile("cp.async.wait_group 2;\n" ::);
        } else {
            asm volatile("cp.async.wait_group 0;\n" ::);
        }
        __syncthreads();

        const __half* As = smem + (kt % NSTG) * STAGE_H;
        const __half* Bs = As + BM * SPADH;
#pragma unroll
        for (int ks = 0; ks < 4; ks++) {
            const int kh = ks * 16 + (lane & 3) * 2;
            // A fragments: 2 m16 tiles (32 rows)
            uint32_t a[2][4];
#pragma unroll
            for (int mi = 0; mi < 2; mi++) {
                const __half* p = As + (warp_m * 32 + mi * 16 + (lane >> 2)) * SPADH + kh;
                a[mi][0] = *reinterpret_cast<const uint32_t*>(p);
                a[mi][1] = *reinterpret_cast<const uint32_t*>(p + 8 * SPADH);
                a[mi][2] = *reinterpret_cast<const uint32_t*>(p + 8);
                a[mi][3] = *reinterpret_cast<const uint32_t*>(p + 8 * SPADH + 8);
            }
            // B fragments: 8 n8 tiles (64 cols)
            uint32_t b[8][2];
#pragma unroll
            for (int nj = 0; nj < 8; nj++) {
                const __half* p = Bs + (warp_n * 64 + nj * 8 + (lane >> 2)) * SPADH + kh;
                b[nj][0] = *reinterpret_cast<const uint32_t*>(p);
                b[nj][1] = *reinterpret_cast<const uint32_t*>(p + 8);
            }
#pragma unroll
            for (int nj = 0; nj < 8; nj++)
#pragma unroll
                for (int mi = 0; mi < 2; mi++)
                    mma_f16(acc[mi][nj], a[mi], b[nj][0], b[nj][1]);
        }
        __syncthreads();
    }

    // epilogue: bias + ReLU, streaming float2 stores
    const int m0 = bm * BM + warp_m * 32;
    const int n0 = bn * BN + warp_n * 64;
#pragma unroll
    for (int nj = 0; nj < 8; nj++) {
        const int n = n0 + nj * 8 + (lane & 3) * 2;
        const float b0 = bias[n];
        const float b1 = bias[n + 1];
#pragma unroll
        for (int mi = 0; mi < 2; mi++) {
            const int m = m0 + mi * 16 + (lane >> 2);
            float2 r0, r1;
            r0.x = fmaxf(acc[mi][nj][0] + b0, 0.f);
            r0.y = fmaxf(acc[mi][nj][1] + b1, 0.f);
            r1.x = fmaxf(acc[mi][nj][2] + b0, 0.f);
            r1.y = fmaxf(acc[mi][nj][3] + b1, 0.f);
            st_cs_f2(out + (size_t)m * DIM + n, r0);
            st_cs_f2(out + (size_t)(m + 8) * DIM + n, r1);
        }
    }
}

// ---------------------------------------------------------------------------
extern "C" void kernel_launch(void* const* d_in, const int* in_sizes, int n_in,
                              void* d_out, int out_size) {
    const float* x     = (const float*)d_in[0];
    const float* W     = (const float*)d_in[1];
    const float* bias  = (const float*)d_in[2];
    const float* gamma = (const float*)d_in[3];
    const float* beta  = (const float*)d_in[4];
    float* out = (float*)d_out;

    round_w_kernel<<<(DIM * (size_t)DIM) / (256 * 4), 256>>>(
        reinterpret_cast<const float4*>(W));
    ln_kernel<<<MTOT, 256>>>(x, gamma, beta);

    cudaFuncSetAttribute(gemm_kernel,
                         cudaFuncAttributeMaxDynamicSharedMemorySize, SMEM_BYTES);
    dim3 grid(DIM / BN, MTOT / BM);  // (32, 128)
    gemm_kernel<<<grid, 256, SMEM_BYTES>>>(bias, out);
}

// round 15
// speedup vs baseline: 2.3140x; 1.0586x over previous
#include <cuda_runtime.h>
#include <cuda_fp16.h>
#include <cstdint>

#define DIM  4096
#define MTOT 16384

// Scratch (device globals — no allocation allowed)
static __device__ __half g_h[(size_t)MTOT * DIM];   // LN output, fp16
static __device__ __half g_wt[(size_t)DIM * DIM];   // W, fp16

// ---------------------------------------------------------------------------
// Kernel 1: W -> fp16
// ---------------------------------------------------------------------------
__global__ void round_w_kernel(const float4* __restrict__ W) {
    size_t i = (size_t)blockIdx.x * blockDim.x + threadIdx.x;
    float4 v = W[i];
    __half2 h0 = __floats2half2_rn(v.x, v.y);
    __half2 h1 = __floats2half2_rn(v.z, v.w);
    uint2 o;
    o.x = *reinterpret_cast<uint32_t*>(&h0);
    o.y = *reinterpret_cast<uint32_t*>(&h1);
    reinterpret_cast<uint2*>(g_wt)[i] = o;
}

// ---------------------------------------------------------------------------
// Kernel 2: LayerNorm -> fp16 into g_h
// ---------------------------------------------------------------------------
__global__ void ln_kernel(const float* __restrict__ x,
                          const float* __restrict__ gamma,
                          const float* __restrict__ beta) {
    __shared__ float rs[8], rq[8];
    const int row = blockIdx.x;
    const int tid = threadIdx.x;
    const float4* xr = reinterpret_cast<const float4*>(x + (size_t)row * DIM);

    float4 v[4];
    float s = 0.f, sq = 0.f;
#pragma unroll
    for (int i = 0; i < 4; i++) {
        v[i] = xr[tid + i * 256];
        s  += v[i].x + v[i].y + v[i].z + v[i].w;
        sq += v[i].x * v[i].x + v[i].y * v[i].y + v[i].z * v[i].z + v[i].w * v[i].w;
    }
#pragma unroll
    for (int off = 16; off > 0; off >>= 1) {
        s  += __shfl_xor_sync(0xffffffffu, s, off);
        sq += __shfl_xor_sync(0xffffffffu, sq, off);
    }
    if ((tid & 31) == 0) { rs[tid >> 5] = s; rq[tid >> 5] = sq; }
    __syncthreads();
    float ts = 0.f, tq = 0.f;
#pragma unroll
    for (int i = 0; i < 8; i++) { ts += rs[i]; tq += rq[i]; }

    const float mean = ts * (1.0f / DIM);
    const float var  = tq * (1.0f / DIM) - mean * mean;
    const float inv  = rsqrtf(var + 1e-5f);

    const float4* gp = reinterpret_cast<const float4*>(gamma);
    const float4* bp = reinterpret_cast<const float4*>(beta);
    uint2* hr = reinterpret_cast<uint2*>(g_h + (size_t)row * DIM);
#pragma unroll
    for (int i = 0; i < 4; i++) {
        const int c = tid + i * 256;
        float4 g = gp[c], be = bp[c];
        __half2 h0 = __floats2half2_rn((v[i].x - mean) * inv * g.x + be.x,
                                       (v[i].y - mean) * inv * g.y + be.y);
        __half2 h1 = __floats2half2_rn((v[i].z - mean) * inv * g.z + be.z,
                                       (v[i].w - mean) * inv * g.w + be.w);
        uint2 o;
        o.x = *reinterpret_cast<uint32_t*>(&h0);
        o.y = *reinterpret_cast<uint32_t*>(&h1);
        hr[c] = o;
    }
}

// ---------------------------------------------------------------------------
// Kernel 3: GEMM  out[m,n] = relu( sum_k h[m,k] * W[n,k] + bias[n] )
// fp16 in, fp32 accum. 128x128x64 CTA tile, 128 threads, 4 warps (2x2),
// warp tile 64x64, ldmatrix.x4 + mma.m16n8k16, 3-stage cp.async, 2 CTAs/SM.
// ---------------------------------------------------------------------------
#define BM 128
#define BN 128
#define BKH 64                           // halfs per k-tile (128 B)
#define NSTG 3
#define SPADH 72                         // halfs per smem row (+8 pad)
#define STAGE_H ((BM + BN) * SPADH)      // halfs per stage = 18432
#define SMEM_BYTES (NSTG * STAGE_H * 2)  // 110592 B

__device__ __forceinline__ void cp_async16(uint32_t smem_dst, const void* gptr) {
    asm volatile("cp.async.cg.shared.global [%0], [%1], 16;\n"
                 :: "r"(smem_dst), "l"(gptr));
}

__device__ __forceinline__ void ldsm_x4(uint32_t& r0, uint32_t& r1,
                                        uint32_t& r2, uint32_t& r3, uint32_t addr) {
    asm volatile("ldmatrix.sync.aligned.m8n8.x4.shared.b16 {%0,%1,%2,%3}, [%4];"
                 : "=r"(r0), "=r"(r1), "=r"(r2), "=r"(r3) : "r"(addr));
}

__device__ __forceinline__ void mma_f16(float* c, const uint32_t* a,
                                        uint32_t b0, uint32_t b1) {
    asm volatile(
        "mma.sync.aligned.m16n8k16.row.col.f32.f16.f16.f32 "
        "{%0,%1,%2,%3}, {%4,%5,%6,%7}, {%8,%9}, {%0,%1,%2,%3};\n"
        : "+f"(c[0]), "+f"(c[1]), "+f"(c[2]), "+f"(c[3])
        : "r"(a[0]), "r"(a[1]), "r"(a[2]), "r"(a[3]), "r"(b0), "r"(b1));
}

__device__ __forceinline__ void st_cs_f2(float* p, float2 v) {
    asm volatile("st.global.cs.v2.f32 [%0], {%1, %2};" :: "l"(p), "f"(v.x), "f"(v.y)
                 : "memory");
}

__global__ void __launch_bounds__(128, 2)
gemm_kernel(const float* __restrict__ bias, float* __restrict__ out) {
    extern __shared__ __half smem[];
    const int tid  = threadIdx.x;
    const int lane = tid & 31;
    const int wid  = tid >> 5;
    const int warp_m = wid >> 1;   // 0..1 -> 64 rows each
    const int warp_n = wid & 1;    // 0..1 -> 64 cols each
    const int bn = blockIdx.x;     // N fastest: A-tile L2 reuse per wave
    const int bm = blockIdx.y;

    const __half* Abase = g_h  + (size_t)(bm * BM) * DIM;
    const __half* Bbase = g_wt + (size_t)(bn * BN) * DIM;
    const uint32_t smem_u = (uint32_t)__cvta_generic_to_shared(smem);

    float acc[4][8][4];
#pragma unroll
    for (int i = 0; i < 4; i++)
#pragma unroll
        for (int j = 0; j < 8; j++)
#pragma unroll
            for (int r = 0; r < 4; r++) acc[i][j][r] = 0.f;

    // ldmatrix lane-address offsets (bytes, within a stage)
    // A x4: lanes 0-15 -> rows 0-15 (k 0-7), lanes 16-31 -> rows 0-15 (k 8-15)
    const uint32_t a_off0 =
        ((uint32_t)(warp_m * 64 + (lane & 15)) * SPADH + (lane >> 4) * 8) * 2u;
    // B x4: matrix m = lane>>3: nj-subtile (m>>1), k-half (m&1); rows lane&7
    const int bmat = lane >> 3;
    const uint32_t b_off0 =
        ((uint32_t)(BM + warp_n * 64 + (bmat >> 1) * 8 + (lane & 7)) * SPADH
         + (bmat & 1) * 8) * 2u;

    // staging: 256 rows x 64 halfs = 2048 chunks of 16B; 16 per thread
    auto issue = [&](int kt) {
        const int s  = kt % NSTG;
        const int k0 = kt * BKH;
        const uint32_t sbase = smem_u + (uint32_t)(s * STAGE_H) * 2u;
#pragma unroll
        for (int i = 0; i < 16; i++) {
            const int c = tid + i * 128;
            const int r = c >> 3;          // 0..255
            const int q = (c & 7) * 8;     // half offset within row
            const uint32_t dst = sbase + (uint32_t)(r * SPADH + q) * 2u;
            const __half* src = (r < BM)
                ? Abase + (size_t)r * DIM + k0 + q
                : Bbase + (size_t)(r - BM) * DIM + k0 + q;
            cp_async16(dst, src);
        }
        asm volatile("cp.async.commit_group;\n" ::);
    };

    const int NK = DIM / BKH;  // 64
    issue(0);
    issue(1);

    for (int kt = 0; kt < NK; kt++) {
        if (kt + 2 < NK) {
            issue(kt + 2);
            asm volatile("cp.async.wait_group 2;\n" ::);
        } else {
            asm volatile("cp.async.wait_group 0;\n" ::);
        }
        __syncthreads();

        const uint32_t sbase = smem_u + (uint32_t)((kt % NSTG) * STAGE_H) * 2u;
        const uint32_t abase = sbase + a_off0;
        const uint32_t bbase = sbase + b_off0;
#pragma unroll
        for (int ks = 0; ks < 4; ks++) {
            const uint32_t kb = (uint32_t)(ks * 16) * 2u;   // 16 halfs
            uint32_t a[4][4];
#pragma unroll
            for (int mi = 0; mi < 4; mi++)
                ldsm_x4(a[mi][0], a[mi][1], a[mi][2], a[mi][3],
                        abase + (uint32_t)(mi * 16 * SPADH) * 2u + kb);
            uint32_t b[8][2];
#pragma unroll
            for (int p = 0; p < 4; p++)
                ldsm_x4(b[2*p][0], b[2*p][1], b[2*p+1][0], b[2*p+1][1],
                        bbase + (uint32_t)(p * 16 * SPADH) * 2u + kb);
#pragma unroll
            for (int nj = 0; nj < 8; nj++)
#pragma unroll
                for (int mi = 0; mi < 4; mi++)
                    mma_f16(acc[mi][nj], a[mi], b[nj][0], b[nj][1]);
        }
        __syncthreads();
    }

    // epilogue: bias + ReLU, streaming float2 stores
    const int m0 = bm * BM + warp_m * 64;
    const int n0 = bn * BN + warp_n * 64;
#pragma unroll
    for (int nj = 0; nj < 8; nj++) {
        const int n = n0 + nj * 8 + (lane & 3) * 2;
        const float b0 = bias[n];
        const float b1 = bias[n + 1];
#pragma unroll
        for (int mi = 0; mi < 4; mi++) {
            const int m = m0 + mi * 16 + (lane >> 2);
            float2 r0, r1;
            r0.x = fmaxf(acc[mi][nj][0] + b0, 0.f);
            r0.y = fmaxf(acc[mi][nj][1] + b1, 0.f);
            r1.x = fmaxf(acc[mi][nj][2] + b0, 0.f);
            r1.y = fmaxf(acc[mi][nj][3] + b1, 0.f);
            st_cs_f2(out + (size_t)m * DIM + n, r0);
            st_cs_f2(out + (size_t)(m + 8) * DIM + n, r1);
        }
    }
}

// ---------------------------------------------------------------------------
extern "C" void kernel_launch(void* const* d_in, const int* in_sizes, int n_in,
                              void* d_out, int out_size) {
    const float* x     = (const float*)d_in[0];
    const float* W     = (const float*)d_in[1];
    const float* bias  = (const float*)d_in[2];
    const float* gamma = (const float*)d_in[3];
    const float* beta  = (const float*)d_in[4];
    float* out = (float*)d_out;

    round_w_kernel<<<(DIM * (size_t)DIM) / (256 * 4), 256>>>(
        reinterpret_cast<const float4*>(W));
    ln_kernel<<<MTOT, 256>>>(x, gamma, beta);

    cudaFuncSetAttribute(gemm_kernel,
                         cudaFuncAttributeMaxDynamicSharedMemorySize, SMEM_BYTES);
    dim3 grid(DIM / BN, MTOT / BM);  // (32, 128)
    gemm_kernel<<<grid, 128, SMEM_BYTES>>>(bias, out);
}